// round 7
// baseline (speedup 1.0000x reference)
#include <cuda_runtime.h>
#include <cstdint>

#define SEQ    512
#define BATCH  512
#define IN_DIM 128
#define NQ     8
#define D_TOT  136   // IN_DIM + NQ

// Scratch: Zx[s][b][o], o = g*8 + q
__device__ float g_zx[(size_t)SEQ * BATCH * 32];

typedef unsigned long long ull;

// --- packed fp32x2 ops (Blackwell; PTX-only) ---
__device__ __forceinline__ ull fma2(ull a, ull b, ull c) {
    ull d; asm("fma.rn.f32x2 %0, %1, %2, %3;" : "=l"(d) : "l"(a), "l"(b), "l"(c)); return d;
}
__device__ __forceinline__ ull mul2(ull a, ull b) {
    ull d; asm("mul.rn.f32x2 %0, %1, %2;" : "=l"(d) : "l"(a), "l"(b)); return d;
}
__device__ __forceinline__ ull add2(ull a, ull b) {
    ull d; asm("add.rn.f32x2 %0, %1, %2;" : "=l"(d) : "l"(a), "l"(b)); return d;
}
__device__ __forceinline__ ull pack2(float lo, float hi) {
    ull d; asm("mov.b64 %0, {%1, %2};" : "=l"(d) : "r"(__float_as_uint(lo)), "r"(__float_as_uint(hi))); return d;
}
__device__ __forceinline__ void unpack2(ull v, float& lo, float& hi) {
    unsigned a, b; asm("mov.b64 {%0, %1}, %2;" : "=r"(a), "=r"(b) : "l"(v));
    lo = __uint_as_float(a); hi = __uint_as_float(b);
}
__device__ __forceinline__ ull dup2(float x) {
    ull d; unsigned u = __float_as_uint(x);
    asm("mov.b64 %0, {%1, %1};" : "=l"(d) : "r"(u)); return d;
}
__device__ __forceinline__ float rcp_fast(float x) {
    float r; asm("rcp.approx.f32 %0, %1;" : "=f"(r) : "f"(x)); return r;
}

// ============================================================================
// Kernel 1: Zx[row][o] = sum_d x[row][d] * W[o][d] + b[o] + qp[o]
//   TWO rows per thread (unchanged).
// ============================================================================
__global__ __launch_bounds__(256) void zx_kernel(
    const float* __restrict__ x, const float* __restrict__ W,
    const float* __restrict__ b, const float* __restrict__ qp)
{
    __shared__ ulonglong2 Ws[IN_DIM * 4];
    __shared__ ulonglong2 Ws_hi[IN_DIM * 4];
    __shared__ float bias[32];

    int tid = threadIdx.x;
    float* WsF   = (float*)Ws;
    float* WsFhi = (float*)Ws_hi;
    for (int i = tid; i < IN_DIM * 32; i += 256) {
        int d = i >> 5, o = i & 31;
        float w = W[o * D_TOT + d];
        if (o < 16) WsF[d * 16 + o] = w;
        else        WsFhi[d * 16 + (o - 16)] = w;
    }
    if (tid < 32) bias[tid] = b[tid] + qp[tid];
    __syncthreads();

    int row0 = blockIdx.x * 512 + tid;
    int row1 = row0 + 256;
    const float4* xr0 = (const float4*)(x + (size_t)row0 * IN_DIM);
    const float4* xr1 = (const float4*)(x + (size_t)row1 * IN_DIM);

    ull acc0[16], acc1[16];
#pragma unroll
    for (int i = 0; i < 16; i++) { acc0[i] = 0ULL; acc1[i] = 0ULL; }

#pragma unroll 2
    for (int d4 = 0; d4 < IN_DIM / 4; d4++) {
        float4 xv0 = xr0[d4];
        float4 xv1 = xr1[d4];
        float xs0[4] = {xv0.x, xv0.y, xv0.z, xv0.w};
        float xs1[4] = {xv1.x, xv1.y, xv1.z, xv1.w};
#pragma unroll
        for (int k = 0; k < 4; k++) {
            int d = d4 * 4 + k;
            ull xa = dup2(xs0[k]);
            ull xb = dup2(xs1[k]);
            const ulonglong2* wlo = Ws    + d * 4;
            const ulonglong2* whi = Ws_hi + d * 4;
#pragma unroll
            for (int j = 0; j < 4; j++) {
                ulonglong2 wp = wlo[j];
                acc0[2 * j]     = fma2(xa, wp.x, acc0[2 * j]);
                acc0[2 * j + 1] = fma2(xa, wp.y, acc0[2 * j + 1]);
                acc1[2 * j]     = fma2(xb, wp.x, acc1[2 * j]);
                acc1[2 * j + 1] = fma2(xb, wp.y, acc1[2 * j + 1]);
            }
#pragma unroll
            for (int j = 0; j < 4; j++) {
                ulonglong2 wp = whi[j];
                acc0[8 + 2 * j]     = fma2(xa, wp.x, acc0[8 + 2 * j]);
                acc0[8 + 2 * j + 1] = fma2(xa, wp.y, acc0[8 + 2 * j + 1]);
                acc1[8 + 2 * j]     = fma2(xb, wp.x, acc1[8 + 2 * j]);
                acc1[8 + 2 * j + 1] = fma2(xb, wp.y, acc1[8 + 2 * j + 1]);
            }
        }
    }

    float4* zr0 = (float4*)(g_zx + (size_t)row0 * 32);
    float4* zr1 = (float4*)(g_zx + (size_t)row1 * 32);
#pragma unroll
    for (int j = 0; j < 8; j++) {
        float e0, e1, e2, e3;
        unpack2(acc0[2 * j], e0, e1); unpack2(acc0[2 * j + 1], e2, e3);
        zr0[j] = make_float4(e0 + bias[4 * j], e1 + bias[4 * j + 1],
                             e2 + bias[4 * j + 2], e3 + bias[4 * j + 3]);
        unpack2(acc1[2 * j], e0, e1); unpack2(acc1[2 * j + 1], e2, e3);
        zr1[j] = make_float4(e0 + bias[4 * j], e1 + bias[4 * j + 1],
                             e2 + bias[4 * j + 2], e3 + bias[4 * j + 3]);
    }
}

// ============================================================================
// One recurrence step for one batch group (8 lanes: lane-in-group = g*2+hf).
// Gate combine via shfl_xor(6)/shfl_xor(2); g0 lanes own c,h.
// ============================================================================
struct GState {
    ull hp[4];        // h pairs (replicated across the 8-lane group)
    ull Cp0, Cp1;     // c pairs (valid on g0 lanes)
    ull H0, H1;       // h pairs produced this step (g0 lanes)
};

__device__ __forceinline__ void rnn_step(
    GState& S, const ull Wp[4][4], float4 z, int hf,
    ull P0, ull P1, ull Q1, ull Q2, ull ob2,
    ull C105, ull C945, ull C15, ull C420)
{
    const unsigned FULL = 0xffffffffu;

    // dot per local row: packed accumulate + horizontal add
    ull ac0 = mul2(S.hp[0], Wp[0][0]);
    ull ac1 = mul2(S.hp[0], Wp[1][0]);
    ull ac2 = mul2(S.hp[0], Wp[2][0]);
    ull ac3 = mul2(S.hp[0], Wp[3][0]);
#pragma unroll
    for (int k = 1; k < 4; k++) {
        ac0 = fma2(S.hp[k], Wp[0][k], ac0);
        ac1 = fma2(S.hp[k], Wp[1][k], ac1);
        ac2 = fma2(S.hp[k], Wp[2][k], ac2);
        ac3 = fma2(S.hp[k], Wp[3][k], ac3);
    }
    float l0, l1, l2, l3, r0, r1, r2, r3;
    unpack2(ac0, l0, r0); unpack2(ac1, l1, r1);
    unpack2(ac2, l2, r2); unpack2(ac3, l3, r3);
    float a0 = __cosf(z.x + l0 + r0);
    float a1 = __cosf(z.y + l1 + r1);
    float a2 = __cosf(z.z + l2 + r2);
    float a3 = __cosf(z.w + l3 + r3);

    // local inclusive cumprod of 4 + cross-half prefix
    float k1 = a0 * a1;
    float t23 = a2 * a3;
    float k2 = k1 * a2;
    float k3 = k1 * t23;
    float T = __shfl_xor_sync(FULL, k3, 1);
    ull M = dup2(hf ? T : 1.0f);
    ull X0 = mul2(M, pack2(a0, k1));
    ull X1 = mul2(M, pack2(k2, k3));

    // gate rational (asc folded into coefficients): v = ob + x(P0+P1 t)/(105+Q1 t+Q2 t^2)
    ull T0 = mul2(X0, X0), T1 = mul2(X1, X1);
    ull N0 = mul2(X0, fma2(P1, T0, P0));
    ull N1 = mul2(X1, fma2(P1, T1, P0));
    ull B0 = fma2(fma2(Q2, T0, Q1), T0, C105);
    ull B1 = fma2(fma2(Q2, T1, Q1), T1, C105);
    float d0, d1, d2, d3, n0, n1, n2, n3;
    unpack2(B0, d0, d1); unpack2(B1, d2, d3);
    unpack2(N0, n0, n1); unpack2(N1, n2, n3);
    float inv0 = rcp_fast(d0 * d1);
    float inv1 = rcp_fast(d2 * d3);
    ull V0 = fma2(pack2(n0 * d1, n1 * d0), dup2(inv0), ob2);
    ull V1 = fma2(pack2(n2 * d3, n3 * d2), dup2(inv1), ob2);

    // gate exchanges: xor6 (f<->o, i<->g), then xor2 (i*g to g0)
    ull t0 = __shfl_xor_sync(FULL, V0, 6);
    ull t1 = __shfl_xor_sync(FULL, V1, 6);
    ull pr0 = mul2(V0, t0);
    ull pr1 = mul2(V1, t1);
    ull ig0 = __shfl_xor_sync(FULL, pr0, 2);
    ull ig1 = __shfl_xor_sync(FULL, pr1, 2);

    // cell update + cell tanh (Pade [5/4])
    S.Cp0 = fma2(V0, S.Cp0, ig0);
    S.Cp1 = fma2(V1, S.Cp1, ig1);
    ull TC0 = mul2(S.Cp0, S.Cp0), TC1 = mul2(S.Cp1, S.Cp1);
    ull NC0 = mul2(S.Cp0, fma2(add2(TC0, C105), TC0, C945));
    ull NC1 = mul2(S.Cp1, fma2(add2(TC1, C105), TC1, C945));
    ull BC0 = fma2(fma2(C15, TC0, C420), TC0, C945);
    ull BC1 = fma2(fma2(C15, TC1, C420), TC1, C945);
    float e0, e1, e2, e3, m0, m1, m2, m3;
    unpack2(BC0, e0, e1); unpack2(BC1, e2, e3);
    unpack2(NC0, m0, m1); unpack2(NC1, m2, m3);
    float iv0 = rcp_fast(e0 * e1);
    float iv1 = rcp_fast(e2 * e3);
    ull TH0 = mul2(pack2(m0 * e1, m1 * e0), dup2(iv0));
    ull TH1 = mul2(pack2(m2 * e3, m3 * e2), dup2(iv1));

    // h = o * tanh(c): t0/t1 on g0 lanes hold o (from g3 via xor6)
    S.H0 = mul2(t0, TH0);
    S.H1 = mul2(t1, TH1);

    // broadcast h pairs from the two g0 lanes of this 8-lane group
    S.hp[0] = __shfl_sync(FULL, S.H0, 0, 8);
    S.hp[1] = __shfl_sync(FULL, S.H1, 0, 8);
    S.hp[2] = __shfl_sync(FULL, S.H0, 1, 8);
    S.hp[3] = __shfl_sync(FULL, S.H1, 1, 8);
}

// ============================================================================
// Kernel 2: recurrence, TWO independent batches per 8-lane group
// (8 batches per warp) — second chain fills first chain's stall slots.
// ============================================================================
__global__ void __launch_bounds__(32, 1) rnn_kernel(
    const float* __restrict__ W, const float* __restrict__ h0,
    const float* __restrict__ c0, float* __restrict__ out)
{
    int lane = threadIdx.x;
    int hf = lane & 1;
    int g  = (lane >> 1) & 3;
    int bl = lane >> 3;                          // group 0..3
    int bA = blockIdx.x * 8 + bl;                // batch A
    int bB = bA + 4;                             // batch B
    bool owner = (g == 0);

    // Row-packed recurrent weights (shared by both batch groups)
    ull Wp[4][4];
#pragma unroll
    for (int r = 0; r < 4; r++)
#pragma unroll
        for (int k = 0; k < 4; k++) {
            const float* wr = W + (g * 8 + 4 * hf + r) * D_TOT + IN_DIM;
            Wp[r][k] = pack2(wr[2 * k], wr[2 * k + 1]);
        }

    GState A, B;
#pragma unroll
    for (int k = 0; k < 4; k++) {
        A.hp[k] = pack2(h0[bA * 8 + 2 * k], h0[bA * 8 + 2 * k + 1]);
        B.hp[k] = pack2(h0[bB * 8 + 2 * k], h0[bB * 8 + 2 * k + 1]);
    }
    {
        float4 cv = *(const float4*)(c0 + bA * 8 + 4 * hf);
        A.Cp0 = pack2(cv.x, cv.y); A.Cp1 = pack2(cv.z, cv.w);
        cv = *(const float4*)(c0 + bB * 8 + 4 * hf);
        B.Cp0 = pack2(cv.x, cv.y); B.Cp1 = pack2(cv.z, cv.w);
    }
    A.H0 = A.H1 = B.H0 = B.H1 = 0ULL;

    // per-lane rational coefficients (asc folded in)
    bool is_g = (g == 2);
    ull P0  = dup2(is_g ? 105.0f : 26.25f);
    ull P1  = dup2(is_g ? 10.0f  : 0.625f);
    ull Q1  = dup2(is_g ? 45.0f  : 11.25f);
    ull Q2  = dup2(is_g ? 1.0f   : 0.0625f);
    ull ob2 = dup2(is_g ? 0.0f   : 0.5f);
    ull C105 = dup2(105.0f), C945 = dup2(945.0f);
    ull C15  = dup2(15.0f),  C420 = dup2(420.0f);

    const float4* zpA = (const float4*)g_zx + ((size_t)bA * 8 + g * 2 + hf);
    const float4* zpB = (const float4*)g_zx + ((size_t)bB * 8 + g * 2 + hf);
    const size_t Z4STRIDE = (size_t)BATCH * 8;

    float4 zbA[4], zbB[4];
#pragma unroll
    for (int u = 0; u < 4; u++) {
        zbA[u] = zpA[(size_t)u * Z4STRIDE];
        zbB[u] = zpB[(size_t)u * Z4STRIDE];
    }

    float4* opA = (float4*)(out + (size_t)bA * 8 + 4 * hf);
    float4* opB = (float4*)(out + (size_t)bB * 8 + 4 * hf);
    const size_t O4STRIDE = (size_t)BATCH * 2;

    for (int s = 0; s < SEQ; s += 4) {
#pragma unroll
        for (int u = 0; u < 4; u++) {
            int sp = s + u + 4; sp = sp < SEQ ? sp : SEQ - 1;
            float4 znA = zpA[(size_t)sp * Z4STRIDE];
            float4 znB = zpB[(size_t)sp * Z4STRIDE];

            rnn_step(A, Wp, zbA[u], hf, P0, P1, Q1, Q2, ob2, C105, C945, C15, C420);
            rnn_step(B, Wp, zbB[u], hf, P0, P1, Q1, Q2, ob2, C105, C945, C15, C420);

            if (owner) {
                float x0, x1, x2, x3;
                unpack2(A.H0, x0, x1); unpack2(A.H1, x2, x3);
                *opA = make_float4(x0, x1, x2, x3);
                unpack2(B.H0, x0, x1); unpack2(B.H1, x2, x3);
                *opB = make_float4(x0, x1, x2, x3);
            }
            opA += O4STRIDE;
            opB += O4STRIDE;

            zbA[u] = znA;
            zbB[u] = znB;
        }
    }

    // Final states: h_f then c_f
    size_t base = (size_t)SEQ * BATCH * 8;
    if (owner) {
        float x0, x1, x2, x3, y0, y1, y2, y3;
        unpack2(A.H0, x0, x1); unpack2(A.H1, x2, x3);
        unpack2(A.Cp0, y0, y1); unpack2(A.Cp1, y2, y3);
        *(float4*)(out + base + (size_t)bA * 8 + 4 * hf) = make_float4(x0, x1, x2, x3);
        *(float4*)(out + base + BATCH * 8 + (size_t)bA * 8 + 4 * hf) = make_float4(y0, y1, y2, y3);
        unpack2(B.H0, x0, x1); unpack2(B.H1, x2, x3);
        unpack2(B.Cp0, y0, y1); unpack2(B.Cp1, y2, y3);
        *(float4*)(out + base + (size_t)bB * 8 + 4 * hf) = make_float4(x0, x1, x2, x3);
        *(float4*)(out + base + BATCH * 8 + (size_t)bB * 8 + 4 * hf) = make_float4(y0, y1, y2, y3);
    }
}

extern "C" void kernel_launch(void* const* d_in, const int* in_sizes, int n_in,
                              void* d_out, int out_size) {
    const float* x  = (const float*)d_in[0];   // inputs (512,512,128)
    const float* h0 = (const float*)d_in[1];   // (512,8)
    const float* c0 = (const float*)d_in[2];   // (512,8)
    const float* W  = (const float*)d_in[3];   // (4,8,136)
    const float* b  = (const float*)d_in[4];   // (4,8)
    const float* qp = (const float*)d_in[5];   // (4,8)
    float* out = (float*)d_out;

    zx_kernel<<<(SEQ * BATCH) / 512, 256>>>(x, W, b, qp);
    rnn_kernel<<<BATCH / 8, 32>>>(W, h0, c0, out);
}

// round 8
// speedup vs baseline: 1.1869x; 1.1869x over previous
#include <cuda_runtime.h>
#include <cstdint>

#define SEQ    512
#define BATCH  512
#define IN_DIM 128
#define NQ     8
#define D_TOT  136   // IN_DIM + NQ

// Scratch: Zx[s][b][o], o = g*8 + q
__device__ float g_zx[(size_t)SEQ * BATCH * 32];

typedef unsigned long long ull;

// --- packed fp32x2 ops (Blackwell; PTX-only) ---
__device__ __forceinline__ ull fma2(ull a, ull b, ull c) {
    ull d; asm("fma.rn.f32x2 %0, %1, %2, %3;" : "=l"(d) : "l"(a), "l"(b), "l"(c)); return d;
}
__device__ __forceinline__ ull mul2(ull a, ull b) {
    ull d; asm("mul.rn.f32x2 %0, %1, %2;" : "=l"(d) : "l"(a), "l"(b)); return d;
}
__device__ __forceinline__ ull add2(ull a, ull b) {
    ull d; asm("add.rn.f32x2 %0, %1, %2;" : "=l"(d) : "l"(a), "l"(b)); return d;
}
__device__ __forceinline__ ull pack2(float lo, float hi) {
    ull d; asm("mov.b64 %0, {%1, %2};" : "=l"(d) : "r"(__float_as_uint(lo)), "r"(__float_as_uint(hi))); return d;
}
__device__ __forceinline__ void unpack2(ull v, float& lo, float& hi) {
    unsigned a, b; asm("mov.b64 {%0, %1}, %2;" : "=r"(a), "=r"(b) : "l"(v));
    lo = __uint_as_float(a); hi = __uint_as_float(b);
}
__device__ __forceinline__ ull dup2(float x) {
    ull d; unsigned u = __float_as_uint(x);
    asm("mov.b64 %0, {%1, %1};" : "=l"(d) : "r"(u)); return d;
}
__device__ __forceinline__ float rcp_fast(float x) {
    float r; asm("rcp.approx.f32 %0, %1;" : "=f"(r) : "f"(x)); return r;
}

// ============================================================================
// Kernel 1: Zx[row][o] = sum_d x[row][d] * W[o][d] + b[o] + qp[o]
//   128 rows/block, d tiled by 32; x staged through smem (coalesced LDG,
//   conflict-free LDS via pad-33 rows); output staged for coalesced STG.
// ============================================================================
#define ZX_ROWS 128
#define ZX_DT   32

__global__ __launch_bounds__(128) void zx_kernel(
    const float* __restrict__ x, const float* __restrict__ W,
    const float* __restrict__ b, const float* __restrict__ qp)
{
    __shared__ ulonglong2 Ws[IN_DIM * 4];     // outputs 0..15 of each d (8KB)
    __shared__ ulonglong2 Ws_hi[IN_DIM * 4];  // outputs 16..31 of each d (8KB)
    __shared__ float bias[32];
    __shared__ float xs[ZX_ROWS * 33];        // pad 33: conflict-free lanes

    int tid = threadIdx.x;
    float* WsF   = (float*)Ws;
    float* WsFhi = (float*)Ws_hi;
    for (int i = tid; i < IN_DIM * 32; i += 128) {
        int d = i >> 5, o = i & 31;
        float w = W[o * D_TOT + d];
        if (o < 16) WsF[d * 16 + o] = w;
        else        WsFhi[d * 16 + (o - 16)] = w;
    }
    if (tid < 32) bias[tid] = b[tid] + qp[tid];

    int rowbase = blockIdx.x * ZX_ROWS;
    const float* xblk = x + (size_t)rowbase * IN_DIM;

    ull acc[16];
#pragma unroll
    for (int i = 0; i < 16; i++) acc[i] = 0ULL;

    for (int t = 0; t < IN_DIM / ZX_DT; t++) {
        __syncthreads();   // covers W staging (t=0) and xs reuse (t>0)
        // cooperative coalesced load: 128 rows x 32 floats
#pragma unroll
        for (int k = 0; k < 8; k++) {
            int idx = tid + k * 128;
            int r = idx >> 3, d4 = idx & 7;
            float4 v = *(const float4*)(xblk + (size_t)r * IN_DIM + t * ZX_DT + d4 * 4);
            float* dst = xs + r * 33 + d4 * 4;
            dst[0] = v.x; dst[1] = v.y; dst[2] = v.z; dst[3] = v.w;
        }
        __syncthreads();

        const float* xr = xs + tid * 33;
#pragma unroll
        for (int dd = 0; dd < ZX_DT; dd++) {
            int d = t * ZX_DT + dd;
            ull xv = dup2(xr[dd]);
            const ulonglong2* wlo = Ws    + d * 4;
            const ulonglong2* whi = Ws_hi + d * 4;
#pragma unroll
            for (int j = 0; j < 4; j++) {
                ulonglong2 wp = wlo[j];
                acc[2 * j]     = fma2(xv, wp.x, acc[2 * j]);
                acc[2 * j + 1] = fma2(xv, wp.y, acc[2 * j + 1]);
            }
#pragma unroll
            for (int j = 0; j < 4; j++) {
                ulonglong2 wp = whi[j];
                acc[8 + 2 * j]     = fma2(xv, wp.x, acc[8 + 2 * j]);
                acc[8 + 2 * j + 1] = fma2(xv, wp.y, acc[8 + 2 * j + 1]);
            }
        }
    }

    // stage z into xs, then cooperative coalesced store
    __syncthreads();
    {
        float* zrow = xs + tid * 33;
#pragma unroll
        for (int j = 0; j < 16; j++) {
            float lo, hi; unpack2(acc[j], lo, hi);
            zrow[2 * j]     = lo + bias[2 * j];
            zrow[2 * j + 1] = hi + bias[2 * j + 1];
        }
    }
    __syncthreads();
#pragma unroll
    for (int k = 0; k < 8; k++) {
        int idx = tid + k * 128;
        int r = idx >> 3, d4 = idx & 7;
        const float* src = xs + r * 33 + d4 * 4;
        float4 v = make_float4(src[0], src[1], src[2], src[3]);
        *(float4*)(g_zx + (size_t)(rowbase + r) * 32 + d4 * 4) = v;
    }
}

// ============================================================================
// Kernel 2: recurrence. 8 lanes/batch: lane = bl*8 + g*2 + hf.
//   Gate exchange: ONE swizzled smem roundtrip (double-buffered, 1 syncwarp);
//   every lane computes c/tanh/h for its q-half redundantly;
//   half-exchange = 2 parallel shfl_xor(1) into permuted-Wp order.
// ============================================================================
__global__ void __launch_bounds__(32, 1) rnn_kernel(
    const float* __restrict__ W, const float* __restrict__ h0,
    const float* __restrict__ c0, float* __restrict__ out)
{
    __shared__ __align__(16) ulonglong2 Vbuf[2][32];   // 1KB, double-buffered

    const unsigned FULL = 0xffffffffu;
    int lane = threadIdx.x;
    int hf = lane & 1;
    int g  = (lane >> 1) & 3;
    int bl = lane >> 3;                       // batch within warp 0..3
    int b  = blockIdx.x * 4 + bl;             // batch 0..511
    bool owner = (g == 0);

    int sw  = bl * 8 + hf * 4 + (g ^ bl);     // swizzled write slot
    int srb = bl * 8 + hf * 4;                // read base; gate G at + (G^bl)

    // Wp[r][k]: W row (g*8 + 4*hf + r), col 128 + qpair. k=0,1 my half; k=2,3 other.
    ull Wp[4][4];
#pragma unroll
    for (int r = 0; r < 4; r++) {
        const float* wr = W + (g * 8 + 4 * hf + r) * D_TOT + IN_DIM;
#pragma unroll
        for (int k = 0; k < 4; k++) {
            int qb = (k < 2) ? (4 * hf + 2 * k) : (4 * (1 - hf) + 2 * (k - 2));
            Wp[r][k] = pack2(wr[qb], wr[qb + 1]);
        }
    }

    // h packets in the same permuted order
    ull hp[4];
    hp[0] = pack2(h0[b * 8 + 4 * hf],           h0[b * 8 + 4 * hf + 1]);
    hp[1] = pack2(h0[b * 8 + 4 * hf + 2],       h0[b * 8 + 4 * hf + 3]);
    hp[2] = pack2(h0[b * 8 + 4 * (1 - hf)],     h0[b * 8 + 4 * (1 - hf) + 1]);
    hp[3] = pack2(h0[b * 8 + 4 * (1 - hf) + 2], h0[b * 8 + 4 * (1 - hf) + 3]);

    // c for my half (redundant across gate lanes)
    float4 cv = *(const float4*)(c0 + b * 8 + 4 * hf);
    ull Cp0 = pack2(cv.x, cv.y);
    ull Cp1 = pack2(cv.z, cv.w);

    // per-lane rational coefficients (asc folded): g-lane tanh vs sigmoid lanes
    bool is_g = (g == 2);
    ull P0  = dup2(is_g ? 105.0f : 26.25f);
    ull P1  = dup2(is_g ? 10.0f  : 0.625f);
    ull Q1  = dup2(is_g ? 45.0f  : 11.25f);
    ull Q2  = dup2(is_g ? 1.0f   : 0.0625f);
    ull ob2 = dup2(is_g ? 0.0f   : 0.5f);
    const ull C105 = dup2(105.0f), C945 = dup2(945.0f);
    const ull C15  = dup2(15.0f),  C420 = dup2(420.0f);

    const float4* zp = (const float4*)g_zx + ((size_t)b * 8 + g * 2 + hf);
    const size_t Z4STRIDE = (size_t)BATCH * 8;

    float4 zb[4];
#pragma unroll
    for (int u = 0; u < 4; u++) zb[u] = zp[(size_t)u * Z4STRIDE];

    float4* op4 = (float4*)(out + (size_t)b * 8 + 4 * hf);
    const size_t O4STRIDE = (size_t)BATCH * 2;

    ull H0 = 0ULL, H1 = 0ULL;

    for (int s = 0; s < SEQ; s += 4) {
#pragma unroll
        for (int u = 0; u < 4; u++) {
            int sp = s + u + 4; sp = sp < SEQ ? sp : SEQ - 1;
            float4 zn = zp[(size_t)sp * Z4STRIDE];

            // dot per row (rows = my half's 4 q's for gate g)
            ull ac0 = mul2(hp[0], Wp[0][0]);
            ull ac1 = mul2(hp[0], Wp[1][0]);
            ull ac2 = mul2(hp[0], Wp[2][0]);
            ull ac3 = mul2(hp[0], Wp[3][0]);
#pragma unroll
            for (int k = 1; k < 4; k++) {
                ac0 = fma2(hp[k], Wp[0][k], ac0);
                ac1 = fma2(hp[k], Wp[1][k], ac1);
                ac2 = fma2(hp[k], Wp[2][k], ac2);
                ac3 = fma2(hp[k], Wp[3][k], ac3);
            }
            float l0, l1, l2, l3, r0, r1, r2, r3;
            unpack2(ac0, l0, r0); unpack2(ac1, l1, r1);
            unpack2(ac2, l2, r2); unpack2(ac3, l3, r3);
            float a0 = __cosf(zb[u].x + l0 + r0);
            float a1 = __cosf(zb[u].y + l1 + r1);
            float a2 = __cosf(zb[u].z + l2 + r2);
            float a3 = __cosf(zb[u].w + l3 + r3);

            // local cumprod of 4 + cross-half prefix (1 scalar shfl)
            float k1 = a0 * a1;
            float t23 = a2 * a3;
            float k2 = k1 * a2;
            float k3 = k1 * t23;
            float T = __shfl_xor_sync(FULL, k3, 1);
            ull M = dup2(hf ? T : 1.0f);
            ull X0 = mul2(M, pack2(a0, k1));
            ull X1 = mul2(M, pack2(k2, k3));

            // gate rational: v = ob + x(P0+P1 t)/(105+Q1 t+Q2 t^2)
            ull T0 = mul2(X0, X0), T1 = mul2(X1, X1);
            ull N0 = mul2(X0, fma2(P1, T0, P0));
            ull N1 = mul2(X1, fma2(P1, T1, P0));
            ull B0 = fma2(fma2(Q2, T0, Q1), T0, C105);
            ull B1 = fma2(fma2(Q2, T1, Q1), T1, C105);
            float d0, d1, d2, d3, n0, n1, n2, n3;
            unpack2(B0, d0, d1); unpack2(B1, d2, d3);
            unpack2(N0, n0, n1); unpack2(N1, n2, n3);
            float inv0 = rcp_fast(d0 * d1);
            float inv1 = rcp_fast(d2 * d3);
            ull V0 = fma2(pack2(n0 * d1, n1 * d0), dup2(inv0), ob2);
            ull V1 = fma2(pack2(n2 * d3, n3 * d2), dup2(inv1), ob2);

            // ONE smem exchange: all 4 gates for my (bl,hf) half
            ulonglong2* buf = Vbuf[u & 1];
            ulonglong2 vpk; vpk.x = V0; vpk.y = V1;
            buf[sw] = vpk;
            __syncwarp(FULL);
            ulonglong2 Fv = buf[srb + (0 ^ bl)];
            ulonglong2 Iv = buf[srb + (1 ^ bl)];
            ulonglong2 Gv = buf[srb + (2 ^ bl)];
            ulonglong2 Ov = buf[srb + (3 ^ bl)];

            // cell update + cell tanh (redundant on all gate lanes)
            Cp0 = fma2(Fv.x, Cp0, mul2(Iv.x, Gv.x));
            Cp1 = fma2(Fv.y, Cp1, mul2(Iv.y, Gv.y));
            ull TC0 = mul2(Cp0, Cp0), TC1 = mul2(Cp1, Cp1);
            ull NC0 = mul2(Cp0, fma2(add2(TC0, C105), TC0, C945));
            ull NC1 = mul2(Cp1, fma2(add2(TC1, C105), TC1, C945));
            ull BC0 = fma2(fma2(C15, TC0, C420), TC0, C945);
            ull BC1 = fma2(fma2(C15, TC1, C420), TC1, C945);
            float e0, e1, e2, e3, m0, m1, m2, m3;
            unpack2(BC0, e0, e1); unpack2(BC1, e2, e3);
            unpack2(NC0, m0, m1); unpack2(NC1, m2, m3);
            float iv0 = rcp_fast(e0 * e1);
            float iv1 = rcp_fast(e2 * e3);
            ull TH0 = mul2(pack2(m0 * e1, m1 * e0), dup2(iv0));
            ull TH1 = mul2(pack2(m2 * e3, m3 * e2), dup2(iv1));

            H0 = mul2(Ov.x, TH0);
            H1 = mul2(Ov.y, TH1);

            // half exchange: 2 parallel shuffles straight into permuted order
            ull Hx0 = __shfl_xor_sync(FULL, H0, 1);
            ull Hx1 = __shfl_xor_sync(FULL, H1, 1);
            hp[0] = H0; hp[1] = H1; hp[2] = Hx0; hp[3] = Hx1;

            if (owner) {
                float x0, x1, x2, x3;
                unpack2(H0, x0, x1); unpack2(H1, x2, x3);
                *op4 = make_float4(x0, x1, x2, x3);
            }
            op4 += O4STRIDE;

            zb[u] = zn;
        }
    }

    // Final states: h_f then c_f (g0 lanes, each owns q-half hf)
    size_t base = (size_t)SEQ * BATCH * 8;
    if (owner) {
        float x0, x1, x2, x3, y0, y1, y2, y3;
        unpack2(H0, x0, x1); unpack2(H1, x2, x3);
        unpack2(Cp0, y0, y1); unpack2(Cp1, y2, y3);
        *(float4*)(out + base + (size_t)b * 8 + 4 * hf) = make_float4(x0, x1, x2, x3);
        *(float4*)(out + base + BATCH * 8 + (size_t)b * 8 + 4 * hf) = make_float4(y0, y1, y2, y3);
    }
}

extern "C" void kernel_launch(void* const* d_in, const int* in_sizes, int n_in,
                              void* d_out, int out_size) {
    const float* x  = (const float*)d_in[0];   // inputs (512,512,128)
    const float* h0 = (const float*)d_in[1];   // (512,8)
    const float* c0 = (const float*)d_in[2];   // (512,8)
    const float* W  = (const float*)d_in[3];   // (4,8,136)
    const float* b  = (const float*)d_in[4];   // (4,8)
    const float* qp = (const float*)d_in[5];   // (4,8)
    float* out = (float*)d_out;

    zx_kernel<<<(SEQ * BATCH) / ZX_ROWS, 128>>>(x, W, b, qp);
    rnn_kernel<<<BATCH / 4, 32>>>(W, h0, c0, out);
}